// round 10
// baseline (speedup 1.0000x reference)
#include <cuda_runtime.h>

// DelayBuffer: out[b, t, i*D + c] = emb[b, t - d_i, c] if t >= d_i else emb[b, t, c]
// d_i in (1, 2, 4, 8, 16, 32) = 1 << i
// B=4, S=4096, D=1024 (fp32). Output [B, S, 6*D].
//
// One block (256 threads) handles TWO consecutive t rows (all 6 delay
// segments each). Each thread front-batches 12 independent float4 loads
// (MLP=12) before issuing 12 streaming float4 stores into two contiguous
// 24 KiB output rows. Input (64 MiB) stays L2-resident; output (402 MiB)
// streams through DRAM with evict-first stores.

static constexpr int B  = 4;
static constexpr int S  = 4096;
static constexpr int D  = 1024;
static constexpr int D4 = D / 4;   // 256 float4 per segment
static constexpr int ND = 6;       // number of delays
static constexpr int TPB = 2;      // t-rows per block

__global__ __launch_bounds__(D4)
void delay_buffer_kernel(const float4* __restrict__ in, float4* __restrict__ out) {
    const int c4 = threadIdx.x;          // 0..255 within a segment
    const int t0 = blockIdx.x * TPB;     // 0..4094 step 2
    const int b  = blockIdx.y;           // 0..3

    // 12 independent loads, front-batched for maximum MLP
    float4 v[TPB][ND];
#pragma unroll
    for (int j = 0; j < TPB; j++) {
        const int t = t0 + j;
#pragma unroll
        for (int i = 0; i < ND; i++) {
            const int d = 1 << i;                      // DELAYS = (1,2,4,8,16,32)
            const int src_t = (t >= d) ? (t - d) : t;
            v[j][i] = __ldg(&in[(b * S + src_t) * D4 + c4]);
        }
    }

    // 12 streaming stores into two contiguous output rows [row, 6*D]
#pragma unroll
    for (int j = 0; j < TPB; j++) {
        const int t = t0 + j;
        float4* orow = out + (size_t)(b * S + t) * (ND * D4) + c4;
#pragma unroll
        for (int i = 0; i < ND; i++) {
            __stcs(orow + i * D4, v[j][i]);
        }
    }
}

extern "C" void kernel_launch(void* const* d_in, const int* in_sizes, int n_in,
                              void* d_out, int out_size) {
    const float4* in = (const float4*)d_in[0];
    float4* out = (float4*)d_out;

    dim3 grid(S / TPB, B);
    delay_buffer_kernel<<<grid, D4>>>(in, out);
}

// round 11
// speedup vs baseline: 1.0079x; 1.0079x over previous
#include <cuda_runtime.h>

// DelayBuffer, input-centric (scatter) formulation.
//
// Forward spec: out[b, t, i*D + c] = emb[b, t - d_i, c] if t >= d_i else emb[b, t, c]
// with d_i = (1, 2, 4, 8, 16, 32) = 1 << i.
//
// Inverted: input row (b, s) is the source of
//   out[b, s + d_i, seg i]   when s + d_i < S   (the t >= d_i case, t = s + d_i)
//   out[b, s,      seg i]   when s < d_i       (the clamped t < d_i case)
// Every (t, seg) output is covered exactly once.
//
// Each block = one (b, s): ONE float4 load per thread (input read from L2
// exactly once, vs 6x in the gather version -> unbinds the LTS throughput
// cap), then 6-7 coalesced 4 KiB streaming segment stores.

static constexpr int B  = 4;
static constexpr int S  = 4096;
static constexpr int D  = 1024;
static constexpr int D4 = D / 4;     // 256 float4 per segment
static constexpr int ND = 6;         // number of delays
static constexpr int ROW4 = ND * D4; // output row width in float4 (1536)

__global__ __launch_bounds__(D4)
void delay_buffer_scatter_kernel(const float4* __restrict__ in,
                                 float4* __restrict__ out) {
    const int c4 = threadIdx.x;      // 0..255 within a segment
    const int s  = blockIdx.x;       // input time index 0..4095
    const int b  = blockIdx.y;       // 0..3

    // single read per thread: input element (b, s, c4)
    const float4 v = __ldg(&in[(b * S + s) * D4 + c4]);

    float4* const obat = out + (size_t)b * S * ROW4;

#pragma unroll
    for (int i = 0; i < ND; i++) {
        const int d = 1 << i;                 // DELAYS = (1,2,4,8,16,32)
        // shifted write: t = s + d (covers all t >= d)
        if (s + d < S)
            __stcs(&obat[(size_t)(s + d) * ROW4 + i * D4 + c4], v);
        // clamped edge write: t = s, only for s < d (covers t < d)
        if (s < d)
            __stcs(&obat[(size_t)s * ROW4 + i * D4 + c4], v);
    }
}

extern "C" void kernel_launch(void* const* d_in, const int* in_sizes, int n_in,
                              void* d_out, int out_size) {
    const float4* in = (const float4*)d_in[0];
    float4* out = (float4*)d_out;

    dim3 grid(S, B);
    delay_buffer_scatter_kernel<<<grid, D4>>>(in, out);
}